// round 3
// baseline (speedup 1.0000x reference)
#include <cuda_runtime.h>
#include <cuda_bf16.h>

// Sparsemax along last axis. Input (4,4096,4096) fp32 -> 16384 rows of D=4096.
// One CTA per row; row lives in registers (256 threads x 16 floats).
// tau found by Michelot/Newton fixed-point on f(tau) = sum(relu(z - tau)) - 1.

#define D      4096
#define NTHR   256
#define V4     4      // float4 chunks per thread (4*4 = 16 floats/thread)

__global__ __launch_bounds__(NTHR)
void sparsemax_kernel(const float* __restrict__ in, float* __restrict__ out) {
    __shared__ float s_sum[8];
    __shared__ float s_cnt[8];
    __shared__ float s_bcast[2];

    const size_t base = (size_t)blockIdx.x * D;
    const float4* rp = reinterpret_cast<const float4*>(in + base);
    float4*       wp = reinterpret_cast<float4*>(out + base);
    const int t    = threadIdx.x;
    const int lane = t & 31;
    const int warp = t >> 5;

    // Coalesced vector load: thread t takes float4 slots t, t+256, t+512, t+768
    float4 v[V4];
#pragma unroll
    for (int j = 0; j < V4; ++j) v[j] = rp[t + NTHR * j];

    // ---- row max (for numerical shift, matching reference) ----
    float m = v[0].x;
#pragma unroll
    for (int j = 0; j < V4; ++j) {
        m = fmaxf(m, fmaxf(fmaxf(v[j].x, v[j].y), fmaxf(v[j].z, v[j].w)));
    }
#pragma unroll
    for (int o = 16; o > 0; o >>= 1) m = fmaxf(m, __shfl_xor_sync(0xffffffffu, m, o));
    if (lane == 0) s_sum[warp] = m;
    __syncthreads();
    if (warp == 0) {
        float mm = s_sum[lane & 7];
#pragma unroll
        for (int o = 4; o > 0; o >>= 1) mm = fmaxf(mm, __shfl_xor_sync(0xffffffffu, mm, o));
        if (lane == 0) s_bcast[0] = mm;
    }
    __syncthreads();
    m = s_bcast[0];

    // ---- shift: z = x - max, so z_max = 0 and tau* in [-1, 0) ----
#pragma unroll
    for (int j = 0; j < V4; ++j) {
        v[j].x -= m; v[j].y -= m; v[j].z -= m; v[j].w -= m;
    }

    // ---- Michelot/Newton: tau <- (S(tau) - 1)/K(tau), monotone from below.
    // Start tau = -1: f(-1) = sum relu(z+1) >= relu(0+1) = 1 >= target, so f(tau0) >= 0.
    float tau = -1.0f;
#pragma unroll 1
    for (int it = 0; it < 32; ++it) {
        float s = 0.0f, c = 0.0f;
#pragma unroll
        for (int j = 0; j < V4; ++j) {
            if (v[j].x > tau) { s += v[j].x; c += 1.0f; }
            if (v[j].y > tau) { s += v[j].y; c += 1.0f; }
            if (v[j].z > tau) { s += v[j].z; c += 1.0f; }
            if (v[j].w > tau) { s += v[j].w; c += 1.0f; }
        }
#pragma unroll
        for (int o = 16; o > 0; o >>= 1) {
            s += __shfl_xor_sync(0xffffffffu, s, o);
            c += __shfl_xor_sync(0xffffffffu, c, o);
        }
        if (lane == 0) { s_sum[warp] = s; s_cnt[warp] = c; }
        __syncthreads();
        if (warp == 0) {
            float ss = s_sum[lane & 7];
            float cc = s_cnt[lane & 7];
#pragma unroll
            for (int o = 4; o > 0; o >>= 1) {
                ss += __shfl_xor_sync(0xffffffffu, ss, o);
                cc += __shfl_xor_sync(0xffffffffu, cc, o);
            }
            if (lane == 0) { s_bcast[0] = ss; s_bcast[1] = cc; }
        }
        __syncthreads();
        const float S = s_bcast[0];
        const float K = s_bcast[1];   // K >= 1 always (z_max = 0 > tau since tau <= tau* < 0)
        const float ntau = (S - 1.0f) / K;
        if (ntau == tau) break;       // uniform across block (broadcast value)
        tau = ntau;
    }

    // ---- emit p = max(z - tau, 0), coalesced vector store ----
#pragma unroll
    for (int j = 0; j < V4; ++j) {
        float4 o;
        o.x = fmaxf(v[j].x - tau, 0.0f);
        o.y = fmaxf(v[j].y - tau, 0.0f);
        o.z = fmaxf(v[j].z - tau, 0.0f);
        o.w = fmaxf(v[j].w - tau, 0.0f);
        wp[t + NTHR * j] = o;
    }
}

extern "C" void kernel_launch(void* const* d_in, const int* in_sizes, int n_in,
                              void* d_out, int out_size) {
    const float* in = (const float*)d_in[0];
    float* out = (float*)d_out;
    const int rows = in_sizes[0] / D;   // 16384
    sparsemax_kernel<<<rows, NTHR>>>(in, out);
}